// round 2
// baseline (speedup 1.0000x reference)
#include <cuda_runtime.h>
#include <math.h>

// Problem constants
#define NN 2048
#define MMDIM 2048
#define C 64
#define TILE_NB 8      // n rows per block
#define TILE_MB 32     // m cols per chunk
#define THREADS 256
#define HS 260         // hidden smem row stride in floats (padded, 16B-aligned rows)

// Dynamic smem layout (float offsets)
#define OFF_HID 0                  // [64][HS]           hidden (silu output), also reused for final reduction
#define OFF_HR  16640              // [32][64]           h_r chunk
#define OFF_W2  18688              // [64][64]           W2
#define OFF_W1  22784              // [3][64]            W1 rows 0..2
#define OFF_C3  22976              // [64]               W1 row3 + b1
#define OFF_B2  23040              // [64]               b2
#define OFF_XL  23104              // [8][3]
#define OFF_LP  23128              // [8][3]
#define OFF_XR  23152              // [32][3]
#define OFF_RP  23248              // [32][3]
#define SMEM_FLOATS 23344
#define SMEM_BYTES (SMEM_FLOATS * 4)

__device__ float g_hagg[NN * C];   // intermediate h_agg between the two kernels

__device__ __forceinline__ float fsigmoid(float x) {
    return 1.0f / (1.0f + __expf(-x));
}

extern __shared__ float sm[];

// ---------------------------------------------------------------------------
// Kernel A: fused edge MLP + sigmoid-weighted aggregation.
// Block = 8 n-rows; loops over m in chunks of 32 (256 pairs per chunk).
// Thread mapping (stage2/3): tid = sn*32 + chg*4 + msl
//   sn  = node row within tile (warp-uniform: warp w handles n-row w)
//   chg = channel group (8 channels each)
//   msl = m-split (covers 8 of the 32 chunk m's)
// ---------------------------------------------------------------------------
__global__ void __launch_bounds__(THREADS, 2)
edge_kernel(const float* __restrict__ h_l, const float* __restrict__ x_l,
            const float* __restrict__ h_r, const float* __restrict__ x_r,
            const float* __restrict__ W1, const float* __restrict__ b1,
            const float* __restrict__ W2, const float* __restrict__ b2)
{
    const int tid = threadIdx.x;
    const int n0  = blockIdx.x * TILE_NB;

    float* hid  = sm + OFF_HID;
    float* hr_s = sm + OFF_HR;
    float* w2s  = sm + OFF_W2;
    float* w1s  = sm + OFF_W1;
    float* c3s  = sm + OFF_C3;
    float* b2s  = sm + OFF_B2;
    float* xls  = sm + OFF_XL;
    float* lps  = sm + OFF_LP;
    float* xrs  = sm + OFF_XR;
    float* rps  = sm + OFF_RP;

    // One-time per-block loads
    for (int i = tid; i < 64 * 64; i += THREADS) w2s[i] = W2[i];
    if (tid < 192) w1s[tid] = W1[tid];                    // W1 rows 0..2
    if (tid < 64) { c3s[tid] = W1[192 + tid] + b1[tid]; b2s[tid] = b2[tid]; }
    if (tid < 24) { xls[tid] = x_l[n0 * 3 + tid]; }
    if (tid >= 32 && tid < 56) {
        int t = tid - 32; int r = t / 3, c = t % 3;
        lps[t] = h_l[(n0 + r) * 64 + 61 + c];
    }

    const int sn  = tid >> 5;          // 0..7  (warp-uniform)
    const int sm1 = tid & 31;          // pair m-index for stage 1
    const int chg = (tid >> 2) & 7;    // 0..7
    const int msl = tid & 3;           // 0..3
    const int chb = chg * 8;

    float acc[8], swa[8];
    #pragma unroll
    for (int i = 0; i < 8; i++) { acc[i] = 0.f; swa[i] = 0.f; }

    for (int m0 = 0; m0 < MMDIM; m0 += TILE_MB) {
        // --- chunk tile loads ---
        if (tid < 96) xrs[tid] = x_r[m0 * 3 + tid];
        if (tid >= 128 && tid < 224) {
            int t = tid - 128; int r = t / 3, c = t % 3;
            rps[t] = h_r[(m0 + r) * 64 + 61 + c];
        }
        {
            const float4* src = (const float4*)(h_r + m0 * 64);
            float4* dst = (float4*)hr_s;
            dst[tid]       = src[tid];
            dst[tid + 256] = src[tid + 256];
        }
        __syncthreads();

        // --- stage 1: per-pair edge scalars + hidden = silu(edge_raw @ W1 + b1) ---
        {
            float dx = xls[sn * 3 + 0] - xrs[sm1 * 3 + 0];
            float dy = xls[sn * 3 + 1] - xrs[sm1 * 3 + 1];
            float dz = xls[sn * 3 + 2] - xrs[sm1 * 3 + 2];
            float d2 = dx * dx + dy * dy + dz * dz;
            float a  = __expf(-0.2f * d2);
            float bh = lps[sn * 3 + 0] * rps[sm1 * 3 + 1] +
                       lps[sn * 3 + 1] * rps[sm1 * 3 + 0];
            float chd = lps[sn * 3 + 2] * rps[sm1 * 3 + 2];
            #pragma unroll 8
            for (int j = 0; j < 64; j++) {
                float pre = fmaf(a, w1s[j],
                            fmaf(bh, w1s[64 + j],
                            fmaf(chd, w1s[128 + j], c3s[j])));
                hid[j * HS + tid] = pre * fsigmoid(pre);
            }
        }
        __syncthreads();

        // --- stage 2: E[8m][8ch] = hidden @ W2 + b2 (register-blocked) ---
        float E[8][8];
        #pragma unroll
        for (int mm2 = 0; mm2 < 8; mm2++)
            #pragma unroll
            for (int cc = 0; cc < 8; cc++) E[mm2][cc] = b2s[chb + cc];

        const int pbase = sn * 32 + msl * 8;
        #pragma unroll 8
        for (int j = 0; j < 64; j++) {
            const float* hp = hid + j * HS + pbase;
            float4 h0 = *(const float4*)hp;
            float4 h1 = *(const float4*)(hp + 4);
            const float* wp = w2s + j * 64 + chb;
            float4 w0 = *(const float4*)wp;
            float4 w1v = *(const float4*)(wp + 4);
            float hv[8] = {h0.x, h0.y, h0.z, h0.w, h1.x, h1.y, h1.z, h1.w};
            float wv[8] = {w0.x, w0.y, w0.z, w0.w, w1v.x, w1v.y, w1v.z, w1v.w};
            #pragma unroll
            for (int mm2 = 0; mm2 < 8; mm2++)
                #pragma unroll
                for (int cc = 0; cc < 8; cc++)
                    E[mm2][cc] = fmaf(hv[mm2], wv[cc], E[mm2][cc]);
        }

        // --- stage 3: w = sigmoid(E); accumulate w*h_r and sum w ---
        #pragma unroll
        for (int mm2 = 0; mm2 < 8; mm2++) {
            const float* hrp = hr_s + (msl * 8 + mm2) * 64 + chb;
            float4 r0 = *(const float4*)hrp;
            float4 r1 = *(const float4*)(hrp + 4);
            float rv[8] = {r0.x, r0.y, r0.z, r0.w, r1.x, r1.y, r1.z, r1.w};
            #pragma unroll
            for (int cc = 0; cc < 8; cc++) {
                float w = fsigmoid(E[mm2][cc]);
                acc[cc] = fmaf(w, rv[cc], acc[cc]);
                swa[cc] += w;
            }
        }
        __syncthreads();
    }

    // --- cross-thread (msl) reduction via smem, then h_agg ---
    float* racc = hid;            // 4*8*64 = 2048 floats
    float* rsw  = hid + 2048;     // 2048 floats
    #pragma unroll
    for (int cc = 0; cc < 8; cc++) {
        racc[(msl * 8 + sn) * 64 + chb + cc] = acc[cc];
        rsw [(msl * 8 + sn) * 64 + chb + cc] = swa[cc];
    }
    __syncthreads();
    for (int i = tid; i < 8 * 64; i += THREADS) {
        int n = i >> 6, c = i & 63;
        float A = 0.f, S = 0.f;
        #pragma unroll
        for (int q = 0; q < 4; q++) {
            A += racc[(q * 8 + n) * 64 + c];
            S += rsw [(q * 8 + n) * 64 + c];
        }
        g_hagg[(n0 + n) * 64 + c] = A / (S + 1e-6f);
    }
}

// ---------------------------------------------------------------------------
// Kernel B: node MLP: z = concat(h_l, h_agg) @ Wn1 + bn1; LN; silu; @ Wn2 + bn2;
// out = h_l + z.   One block (64 threads) per node; thread = output channel.
// ---------------------------------------------------------------------------
__global__ void node_kernel(const float* __restrict__ h_l,
                            const float* __restrict__ Wn1, const float* __restrict__ bn1,
                            const float* __restrict__ ln_g, const float* __restrict__ ln_b,
                            const float* __restrict__ Wn2, const float* __restrict__ bn2,
                            float* __restrict__ out)
{
    __shared__ float ins[128];
    __shared__ float zs[64];
    __shared__ float ss[64];
    const int n = blockIdx.x;
    const int k = threadIdx.x;

    ins[k]      = h_l[n * 64 + k];
    ins[64 + k] = g_hagg[n * 64 + k];
    __syncthreads();

    float z = bn1[k];
    #pragma unroll 16
    for (int i = 0; i < 128; i++) z = fmaf(ins[i], Wn1[i * 64 + k], z);
    zs[k] = z;
    __syncthreads();

    float mu = 0.f;
    #pragma unroll 16
    for (int i = 0; i < 64; i++) mu += zs[i];
    mu *= (1.0f / 64.0f);
    float var = 0.f;
    #pragma unroll 16
    for (int i = 0; i < 64; i++) { float d = zs[i] - mu; var = fmaf(d, d, var); }
    var *= (1.0f / 64.0f);

    float zn = (z - mu) * rsqrtf(var + 1e-5f) * ln_g[k] + ln_b[k];
    ss[k] = zn * fsigmoid(zn);
    __syncthreads();

    float o = bn2[k];
    #pragma unroll 16
    for (int i = 0; i < 64; i++) o = fmaf(ss[i], Wn2[i * 64 + k], o);
    out[n * 64 + k] = ins[k] + o;
}

extern "C" void kernel_launch(void* const* d_in, const int* in_sizes, int n_in,
                              void* d_out, int out_size)
{
    const float* h_l  = (const float*)d_in[0];
    const float* x_l  = (const float*)d_in[1];
    const float* h_r  = (const float*)d_in[2];
    const float* x_r  = (const float*)d_in[3];
    const float* W1   = (const float*)d_in[4];
    const float* b1   = (const float*)d_in[5];
    const float* W2   = (const float*)d_in[6];
    const float* b2   = (const float*)d_in[7];
    const float* Wn1  = (const float*)d_in[8];
    const float* bn1  = (const float*)d_in[9];
    const float* ln_g = (const float*)d_in[10];
    const float* ln_b = (const float*)d_in[11];
    const float* Wn2  = (const float*)d_in[12];
    const float* bn2  = (const float*)d_in[13];
    float* out = (float*)d_out;

    cudaFuncSetAttribute(edge_kernel,
                         cudaFuncAttributeMaxDynamicSharedMemorySize, SMEM_BYTES);

    edge_kernel<<<NN / TILE_NB, THREADS, SMEM_BYTES>>>(h_l, x_l, h_r, x_r,
                                                       W1, b1, W2, b2);
    node_kernel<<<NN, 64>>>(h_l, Wn1, bn1, ln_g, ln_b, Wn2, bn2, out);
}

// round 5
// speedup vs baseline: 4.8082x; 4.8082x over previous
#include <cuda_runtime.h>
#include <cuda_fp16.h>
#include <cstdint>

#define NN 2048
#define MMT 2048
#define THREADS 256
#define TILE_MB 16
#define HRS 68

__device__ float g_hagg[NN * 64];

__device__ __forceinline__ float tanh_ap(float x) {
    float y; asm("tanh.approx.f32 %0, %1;" : "=f"(y) : "f"(x)); return y;
}
// pack two fp32 -> f16x2 register (lo = a, hi = b)
__device__ __forceinline__ uint32_t pack_h2(float lo, float hi) {
    uint32_t u; asm("cvt.rn.f16x2.f32 %0, %1, %2;" : "=r"(u) : "f"(hi), "f"(lo)); return u;
}
__device__ __forceinline__ void mma_f16(float& d0, float& d1, float& d2, float& d3,
                                        uint32_t a0, uint32_t a1, uint32_t a2, uint32_t a3,
                                        uint32_t b0, uint32_t b1) {
    asm volatile(
        "mma.sync.aligned.m16n8k16.row.col.f32.f16.f16.f32 "
        "{%0,%1,%2,%3}, {%4,%5,%6,%7}, {%8,%9}, {%0,%1,%2,%3};"
        : "+f"(d0), "+f"(d1), "+f"(d2), "+f"(d3)
        : "r"(a0), "r"(a1), "r"(a2), "r"(a3), "r"(b0), "r"(b1));
}

// ---------------------------------------------------------------------------
// Edge kernel: block = 8 n-rows (one per warp), loop over m in chunks of 16.
// Pair tile = 128 rows (warp w owns rows w*16..w*16+15, i.e. n = n0+w, mi 0..15).
// E = hidden @ W2 via fp16 mma.sync m16n8k16; hidden generated in registers.
// ---------------------------------------------------------------------------
__global__ void __launch_bounds__(THREADS, 2)
edge_kernel(const float* __restrict__ h_l, const float* __restrict__ x_l,
            const float* __restrict__ h_r, const float* __restrict__ x_r,
            const float* __restrict__ W1, const float* __restrict__ b1,
            const float* __restrict__ W2, const float* __restrict__ b2)
{
    // B fragments of W2 in mma order. Layout [kt][nt][q][r] -> bank-bijective.
    __shared__ uint32_t b0p[1024];
    __shared__ uint32_t b1p[1024];
    __shared__ float w1p[256];     // [row(W1_0,W1_1,W1_2,c3)][kt][q][u]
    __shared__ float hrs[16 * HRS];
    __shared__ float xrs[48];
    __shared__ float rps[48];
    __shared__ float hb2[64];

    const int tid = threadIdx.x;
    const int w   = tid >> 5;
    const int lane = tid & 31;
    const int r = lane >> 2;       // mma groupID (row)
    const int q = lane & 3;        // mma threadID_in_group (col/k residue)
    const int n0 = blockIdx.x * 8;

    // ---- one-time: permuted W2 fragments (fp16) ----
    for (int i = tid; i < 1024; i += THREADS) {
        int rr = i & 7, qq = (i >> 3) & 3, nt = (i >> 5) & 7, kt = i >> 8;
        int c  = nt * 8 + rr;
        int j0 = kt * 16 + 2 * qq;
        b0p[i] = pack_h2(W2[j0 * 64 + c],       W2[(j0 + 1) * 64 + c]);
        b1p[i] = pack_h2(W2[(j0 + 8) * 64 + c], W2[(j0 + 9) * 64 + c]);
    }
    // ---- one-time: permuted W1/c3: tid = row*64 + kt*16 + q*4 + u ----
    {
        int u = tid & 3, qq = (tid >> 2) & 3, kt = (tid >> 4) & 3, row = tid >> 6;
        int jl = (u < 2) ? (2 * qq + u) : (2 * qq + 8 + (u - 2));
        int j  = kt * 16 + jl;
        w1p[tid] = (row < 3) ? W1[row * 64 + j] : (W1[192 + j] + b1[j]);
    }
    if (tid < 64) hb2[tid] = 0.5f * b2[tid];

    // per-warp (n-row) invariants — uniform across warp, LDG broadcast
    const int nrow = n0 + w;
    const float xlx = x_l[nrow * 3 + 0];
    const float xly = x_l[nrow * 3 + 1];
    const float xlz = x_l[nrow * 3 + 2];
    const float l0  = h_l[nrow * 64 + 61];
    const float l1  = h_l[nrow * 64 + 62];
    const float l2  = h_l[nrow * 64 + 63];

    float acc[16], swa[16];
    #pragma unroll
    for (int i = 0; i < 16; i++) { acc[i] = 0.f; swa[i] = 0.f; }

    const int mi0 = r, mi1 = r + 8;

    __syncthreads();

    for (int m0 = 0; m0 < MMT; m0 += TILE_MB) {
        // ---- chunk loads ----
        if (tid < 48) xrs[tid] = x_r[m0 * 3 + tid];
        else if (tid < 96) {
            int t = tid - 48;
            rps[t] = h_r[(m0 + t / 3) * 64 + 61 + t % 3];
        }
        {
            int m = tid >> 4, qq = tid & 15;
            float4 v = ((const float4*)(h_r + m0 * 64))[tid];
            *(float4*)(hrs + m * HRS + qq * 4) = v;
        }
        __syncthreads();

        // ---- stage 1 scalars for this thread's two m-rows ----
        float a0v, bh0, ch0, a1v, bh1, ch1;
        {
            float dx = xlx - xrs[mi0 * 3 + 0];
            float dy = xly - xrs[mi0 * 3 + 1];
            float dz = xlz - xrs[mi0 * 3 + 2];
            float d2 = fmaf(dx, dx, fmaf(dy, dy, dz * dz));
            a0v = __expf(-0.2f * d2);
            bh0 = fmaf(l0, rps[mi0 * 3 + 1], l1 * rps[mi0 * 3 + 0]);
            ch0 = l2 * rps[mi0 * 3 + 2];
        }
        {
            float dx = xlx - xrs[mi1 * 3 + 0];
            float dy = xly - xrs[mi1 * 3 + 1];
            float dz = xlz - xrs[mi1 * 3 + 2];
            float d2 = fmaf(dx, dx, fmaf(dy, dy, dz * dz));
            a1v = __expf(-0.2f * d2);
            bh1 = fmaf(l0, rps[mi1 * 3 + 1], l1 * rps[mi1 * 3 + 0]);
            ch1 = l2 * rps[mi1 * 3 + 2];
        }

        // ---- fused stage1(hidden)+MMA: D[nt] = hidden @ W2 ----
        float D[8][4];
        #pragma unroll
        for (int nt = 0; nt < 8; nt++)
            #pragma unroll
            for (int u = 0; u < 4; u++) D[nt][u] = 0.f;

        #pragma unroll
        for (int kt = 0; kt < 4; kt++) {
            const float4 W0 = *(const float4*)&w1p[(0 * 4 + kt) * 16 + q * 4];
            const float4 Wb = *(const float4*)&w1p[(1 * 4 + kt) * 16 + q * 4];
            const float4 Wc = *(const float4*)&w1p[(2 * 4 + kt) * 16 + q * 4];
            const float4 C3 = *(const float4*)&w1p[(3 * 4 + kt) * 16 + q * 4];
            const float w0v[4] = {W0.x, W0.y, W0.z, W0.w};
            const float wbv[4] = {Wb.x, Wb.y, Wb.z, Wb.w};
            const float wcv[4] = {Wc.x, Wc.y, Wc.z, Wc.w};
            const float c3v[4] = {C3.x, C3.y, C3.z, C3.w};

            float h0[4], h1[4];
            #pragma unroll
            for (int u = 0; u < 4; u++) {
                float p0 = fmaf(a0v, w0v[u], fmaf(bh0, wbv[u], fmaf(ch0, wcv[u], c3v[u])));
                h0[u] = p0 * fmaf(0.5f, tanh_ap(0.5f * p0), 0.5f);
                float p1 = fmaf(a1v, w0v[u], fmaf(bh1, wbv[u], fmaf(ch1, wcv[u], c3v[u])));
                h1[u] = p1 * fmaf(0.5f, tanh_ap(0.5f * p1), 0.5f);
            }
            uint32_t a0 = pack_h2(h0[0], h0[1]);
            uint32_t a2 = pack_h2(h0[2], h0[3]);
            uint32_t a1 = pack_h2(h1[0], h1[1]);
            uint32_t a3 = pack_h2(h1[2], h1[3]);

            const int bbase = kt * 256 + q * 8 + r;
            #pragma unroll
            for (int nt = 0; nt < 8; nt++) {
                uint32_t b0 = b0p[bbase + nt * 32];
                uint32_t b1v = b1p[bbase + nt * 32];
                mma_f16(D[nt][0], D[nt][1], D[nt][2], D[nt][3], a0, a1, a2, a3, b0, b1v);
            }
        }

        // ---- stage 3: w = sigmoid(E + b2); accumulate w*h_r and sum w ----
        #pragma unroll
        for (int nt = 0; nt < 8; nt++) {
            const int c0 = nt * 8 + 2 * q;
            float2 hr0 = *(const float2*)(hrs + mi0 * HRS + c0);
            float2 hr1 = *(const float2*)(hrs + mi1 * HRS + c0);
            float bb0 = hb2[c0], bb1 = hb2[c0 + 1];
            float w00 = fmaf(0.5f, tanh_ap(fmaf(0.5f, D[nt][0], bb0)), 0.5f);
            float w01 = fmaf(0.5f, tanh_ap(fmaf(0.5f, D[nt][1], bb1)), 0.5f);
            float w10 = fmaf(0.5f, tanh_ap(fmaf(0.5f, D[nt][2], bb0)), 0.5f);
            float w11 = fmaf(0.5f, tanh_ap(fmaf(0.5f, D[nt][3], bb1)), 0.5f);
            acc[nt * 2 + 0] += fmaf(w00, hr0.x, w10 * hr1.x);
            acc[nt * 2 + 1] += fmaf(w01, hr0.y, w11 * hr1.y);
            swa[nt * 2 + 0] += w00 + w10;
            swa[nt * 2 + 1] += w01 + w11;
        }
        __syncthreads();
    }

    // ---- reduce over r (lanes differing in bits 2..4), write h_agg ----
    #pragma unroll
    for (int j = 0; j < 16; j++) {
        #pragma unroll
        for (int off = 4; off <= 16; off <<= 1) {
            acc[j] += __shfl_xor_sync(0xffffffffu, acc[j], off);
            swa[j] += __shfl_xor_sync(0xffffffffu, swa[j], off);
        }
    }
    if (lane < 4) {   // r == 0, q = lane
        #pragma unroll
        for (int nt = 0; nt < 8; nt++) {
            int c0 = nt * 8 + 2 * q;
            float2 o;
            o.x = acc[nt * 2 + 0] / (swa[nt * 2 + 0] + 1e-6f);
            o.y = acc[nt * 2 + 1] / (swa[nt * 2 + 1] + 1e-6f);
            *(float2*)(g_hagg + nrow * 64 + c0) = o;
        }
    }
}

// ---------------------------------------------------------------------------
// Node MLP: z = concat(h_l,h_agg)@Wn1+bn1; LN; silu; @Wn2+bn2; out = h_l+z
// ---------------------------------------------------------------------------
__device__ __forceinline__ float fsigmoid(float x) { return 1.0f / (1.0f + __expf(-x)); }

__global__ void node_kernel(const float* __restrict__ h_l,
                            const float* __restrict__ Wn1, const float* __restrict__ bn1,
                            const float* __restrict__ ln_g, const float* __restrict__ ln_b,
                            const float* __restrict__ Wn2, const float* __restrict__ bn2,
                            float* __restrict__ out)
{
    __shared__ float ins[128];
    __shared__ float zs[64];
    __shared__ float ss[64];
    const int n = blockIdx.x;
    const int k = threadIdx.x;

    ins[k]      = h_l[n * 64 + k];
    ins[64 + k] = g_hagg[n * 64 + k];
    __syncthreads();

    float z = bn1[k];
    #pragma unroll 16
    for (int i = 0; i < 128; i++) z = fmaf(ins[i], Wn1[i * 64 + k], z);
    zs[k] = z;
    __syncthreads();

    float mu = 0.f;
    #pragma unroll 16
    for (int i = 0; i < 64; i++) mu += zs[i];
    mu *= (1.0f / 64.0f);
    float var = 0.f;
    #pragma unroll 16
    for (int i = 0; i < 64; i++) { float d = zs[i] - mu; var = fmaf(d, d, var); }
    var *= (1.0f / 64.0f);

    float zn = (z - mu) * rsqrtf(var + 1e-5f) * ln_g[k] + ln_b[k];
    ss[k] = zn * fsigmoid(zn);
    __syncthreads();

    float o = bn2[k];
    #pragma unroll 16
    for (int i = 0; i < 64; i++) o = fmaf(ss[i], Wn2[i * 64 + k], o);
    out[n * 64 + k] = ins[k] + o;
}

extern "C" void kernel_launch(void* const* d_in, const int* in_sizes, int n_in,
                              void* d_out, int out_size)
{
    const float* h_l  = (const float*)d_in[0];
    const float* x_l  = (const float*)d_in[1];
    const float* h_r  = (const float*)d_in[2];
    const float* x_r  = (const float*)d_in[3];
    const float* W1   = (const float*)d_in[4];
    const float* b1   = (const float*)d_in[5];
    const float* W2   = (const float*)d_in[6];
    const float* b2   = (const float*)d_in[7];
    const float* Wn1  = (const float*)d_in[8];
    const float* bn1  = (const float*)d_in[9];
    const float* ln_g = (const float*)d_in[10];
    const float* ln_b = (const float*)d_in[11];
    const float* Wn2  = (const float*)d_in[12];
    const float* bn2  = (const float*)d_in[13];
    float* out = (float*)d_out;

    edge_kernel<<<NN / 8, THREADS>>>(h_l, x_l, h_r, x_r, W1, b1, W2, b2);
    node_kernel<<<NN, 64>>>(h_l, Wn1, bn1, ln_g, ln_b, Wn2, bn2, out);
}

// round 6
// speedup vs baseline: 5.4637x; 1.1363x over previous
#include <cuda_runtime.h>
#include <cuda_fp16.h>
#include <cstdint>

#define NN 2048
#define MMT 2048
#define THREADS 256
#define TILE_MB 16
#define HRS 72
#define H05C 0x38003800u   // half2(0.5, 0.5)

__device__ __forceinline__ float tanh_ap(float x) {
    float y; asm("tanh.approx.f32 %0, %1;" : "=f"(y) : "f"(x)); return y;
}
__device__ __forceinline__ uint32_t pack_h2(float lo, float hi) {
    uint32_t u; asm("cvt.rn.f16x2.f32 %0, %1, %2;" : "=r"(u) : "f"(hi), "f"(lo)); return u;
}
__device__ __forceinline__ uint32_t h2mul(uint32_t a, uint32_t b) {
    uint32_t d; asm("mul.rn.f16x2 %0, %1, %2;" : "=r"(d) : "r"(a), "r"(b)); return d;
}
__device__ __forceinline__ uint32_t h2fma(uint32_t a, uint32_t b, uint32_t c) {
    uint32_t d; asm("fma.rn.f16x2 %0, %1, %2, %3;" : "=r"(d) : "r"(a), "r"(b), "r"(c)); return d;
}
__device__ __forceinline__ uint32_t h2tanh(uint32_t a) {
    uint32_t d; asm("tanh.approx.f16x2 %0, %1;" : "=r"(d) : "r"(a)); return d;
}
__device__ __forceinline__ float2 h22f2(uint32_t u) {
    float2 f;
    asm("{ .reg .b16 lo, hi; mov.b32 {lo, hi}, %2; cvt.f32.f16 %0, lo; cvt.f32.f16 %1, hi; }"
        : "=f"(f.x), "=f"(f.y) : "r"(u));
    return f;
}
// silu on a packed f16x2 pair: s = hp*tanh(hp) + hp, hp = 0.5*p
__device__ __forceinline__ uint32_t silu_h2(uint32_t p) {
    uint32_t hp = h2mul(p, H05C);
    uint32_t t  = h2tanh(hp);
    return h2fma(hp, t, hp);
}
__device__ __forceinline__ void mma_k8(float* D, uint32_t a0, uint32_t a1, uint32_t b0) {
    asm volatile(
        "mma.sync.aligned.m16n8k8.row.col.f32.f16.f16.f32 "
        "{%0,%1,%2,%3}, {%4,%5}, {%6}, {%0,%1,%2,%3};"
        : "+f"(D[0]), "+f"(D[1]), "+f"(D[2]), "+f"(D[3])
        : "r"(a0), "r"(a1), "r"(b0));
}
__device__ __forceinline__ void mma_k16(float& d0, float& d1, float& d2, float& d3,
                                        uint32_t a0, uint32_t a1, uint32_t a2, uint32_t a3,
                                        uint32_t b0, uint32_t b1) {
    asm volatile(
        "mma.sync.aligned.m16n8k16.row.col.f32.f16.f16.f32 "
        "{%0,%1,%2,%3}, {%4,%5,%6,%7}, {%8,%9}, {%0,%1,%2,%3};"
        : "+f"(d0), "+f"(d1), "+f"(d2), "+f"(d3)
        : "r"(a0), "r"(a1), "r"(a2), "r"(a3), "r"(b0), "r"(b1));
}

// ---------------------------------------------------------------------------
// Fully fused kernel. Block = 8 n-rows (warp w owns node n0+w).
// Phase 1 (all warps): loop m chunks of 16; per chunk:
//   MMA1: P = ER(4->8 pad) @ W1  (m16n8k8 x8)   [pre-activation]
//   silu in f16x2  ->  A fragments of MMA2
//   MMA2: E = hidden @ W2        (m16n8k16 x32)
//   sigmoid(E+b2) in f16x2 -> accumulate w*h_r, sum w  (fp32)
// Phase 2 (per-warp): node MLP on h_agg, write output. No global intermediate.
// ---------------------------------------------------------------------------
__global__ void __launch_bounds__(THREADS, 2)
fused_kernel(const float* __restrict__ h_l, const float* __restrict__ x_l,
             const float* __restrict__ h_r, const float* __restrict__ x_r,
             const float* __restrict__ W1, const float* __restrict__ b1,
             const float* __restrict__ W2, const float* __restrict__ b2,
             const float* __restrict__ Wn1, const float* __restrict__ bn1,
             const float* __restrict__ ln_g, const float* __restrict__ ln_b,
             const float* __restrict__ Wn2, const float* __restrict__ bn2,
             float* __restrict__ out)
{
    __shared__ uint2 b2p[1024];          // W2 fragments {b0,b1} [kt][nt][q][r]
    __shared__ float hrs[2][16 * HRS];
    __shared__ float xrs[2][48];
    __shared__ float rps[2][48];
    __shared__ float hagg_s[8][64];
    __shared__ float ss_s[8][64];

    const int tid  = threadIdx.x;
    const int w    = tid >> 5;
    const int lane = tid & 31;
    const int r    = lane >> 2;
    const int q    = lane & 3;
    const int n0   = blockIdx.x * 8;

    // ---- one-time: W2 fragments ----
    for (int i = tid; i < 1024; i += THREADS) {
        int rr = i & 7, qq = (i >> 3) & 3, nt = (i >> 5) & 7, kt = i >> 8;
        int c  = nt * 8 + rr;
        int j0 = kt * 16 + 2 * qq;
        b2p[i] = make_uint2(pack_h2(W2[j0 * 64 + c],       W2[(j0 + 1) * 64 + c]),
                            pack_h2(W2[(j0 + 8) * 64 + c], W2[(j0 + 9) * 64 + c]));
    }
    // ---- one-time: W1 B-fragments (registers, loop-invariant) ----
    uint32_t b1f[8];
    #pragma unroll
    for (int nt = 0; nt < 8; nt++) {
        int cc = nt * 8 + r;
        b1f[nt] = (q == 0) ? pack_h2(W1[cc], W1[64 + cc])
                : (q == 1) ? pack_h2(W1[128 + cc], W1[192 + cc] + b1[cc])
                : 0u;
    }
    // ---- one-time: 0.5*b2 as half2 per nt ----
    uint32_t hb2h[8];
    #pragma unroll
    for (int nt = 0; nt < 8; nt++) {
        int c0 = nt * 8 + 2 * q;
        hb2h[nt] = pack_h2(0.5f * b2[c0], 0.5f * b2[c0 + 1]);
    }

    // per-warp n-row invariants
    const int nrow = n0 + w;
    const float xlx = x_l[nrow * 3 + 0];
    const float xly = x_l[nrow * 3 + 1];
    const float xlz = x_l[nrow * 3 + 2];
    const float l0  = h_l[nrow * 64 + 61];
    const float l1  = h_l[nrow * 64 + 62];
    const float l2  = h_l[nrow * 64 + 63];

    const int mi0 = r, mi1 = r + 8;

    float acc[16], swa[16];
    #pragma unroll
    for (int i = 0; i < 16; i++) { acc[i] = 0.f; swa[i] = 0.f; }

    // ---- chunk-load helper (macro to keep addressing identical) ----
    #define LOAD_CHUNK(m0_, buf_) do {                                         \
        if (tid < 48) xrs[buf_][tid] = x_r[(m0_) * 3 + tid];                   \
        else if (tid < 96) {                                                   \
            int t = tid - 48;                                                  \
            rps[buf_][t] = h_r[((m0_) + t / 3) * 64 + 61 + t % 3];             \
        }                                                                      \
        {                                                                      \
            int mm = tid >> 4, qq = tid & 15;                                  \
            float4 v = ((const float4*)(h_r + (m0_) * 64))[tid];               \
            *(float4*)(&hrs[buf_][mm * HRS + qq * 4]) = v;                     \
        }                                                                      \
    } while (0)

    LOAD_CHUNK(0, 0);
    int buf = 0;

    for (int chunk = 0; chunk < MMT / TILE_MB; chunk++) {
        __syncthreads();
        if (chunk + 1 < MMT / TILE_MB) LOAD_CHUNK((chunk + 1) * TILE_MB, buf ^ 1);

        const float* xr = xrs[buf];
        const float* rp = rps[buf];
        const float* h0base = &hrs[buf][mi0 * HRS];
        const float* h1base = &hrs[buf][mi1 * HRS];

        // ---- edge scalars for this lane's two m-rows ----
        float a0v, bh0, ch0, a1v, bh1, ch1;
        {
            float dx = xlx - xr[mi0 * 3 + 0];
            float dy = xly - xr[mi0 * 3 + 1];
            float dz = xlz - xr[mi0 * 3 + 2];
            float d2 = fmaf(dx, dx, fmaf(dy, dy, dz * dz));
            a0v = __expf(-0.2f * d2);
            bh0 = fmaf(l0, rp[mi0 * 3 + 1], l1 * rp[mi0 * 3 + 0]);
            ch0 = l2 * rp[mi0 * 3 + 2];
        }
        {
            float dx = xlx - xr[mi1 * 3 + 0];
            float dy = xly - xr[mi1 * 3 + 1];
            float dz = xlz - xr[mi1 * 3 + 2];
            float d2 = fmaf(dx, dx, fmaf(dy, dy, dz * dz));
            a1v = __expf(-0.2f * d2);
            bh1 = fmaf(l0, rp[mi1 * 3 + 1], l1 * rp[mi1 * 3 + 0]);
            ch1 = l2 * rp[mi1 * 3 + 2];
        }

        // ---- ER A-fragments (rows mi0, mi1; k-slice 2q,2q+1 of [a,bh,ch,1,0..]) ----
        float e00 = (q == 0) ? a0v : (q == 1) ? ch0 : 0.f;
        float e01 = (q == 0) ? bh0 : (q == 1) ? 1.f : 0.f;
        float e10 = (q == 0) ? a1v : (q == 1) ? ch1 : 0.f;
        float e11 = (q == 0) ? bh1 : (q == 1) ? 1.f : 0.f;
        uint32_t A10 = pack_h2(e00, e01);
        uint32_t A11 = pack_h2(e10, e11);

        // ---- MMA1 + f16x2 silu -> MMA2 A-fragments ----
        uint32_t A2[4][4];
        #pragma unroll
        for (int kt = 0; kt < 4; kt++) {
            float P0[4] = {0.f, 0.f, 0.f, 0.f};
            float P1[4] = {0.f, 0.f, 0.f, 0.f};
            mma_k8(P0, A10, A11, b1f[2 * kt]);
            mma_k8(P1, A10, A11, b1f[2 * kt + 1]);
            A2[kt][0] = silu_h2(pack_h2(P0[0], P0[1]));   // row r,   cols 16kt+2q..
            A2[kt][1] = silu_h2(pack_h2(P0[2], P0[3]));   // row r+8
            A2[kt][2] = silu_h2(pack_h2(P1[0], P1[1]));   // row r,   cols 16kt+8+2q..
            A2[kt][3] = silu_h2(pack_h2(P1[2], P1[3]));   // row r+8
        }

        // ---- MMA2 per n-tile + f16x2 sigmoid + accumulate ----
        const int q8r = q * 8 + r;
        #pragma unroll
        for (int nt = 0; nt < 8; nt++) {
            float D0 = 0.f, D1 = 0.f, D2 = 0.f, D3 = 0.f;
            #pragma unroll
            for (int kt = 0; kt < 4; kt++) {
                uint2 bb = b2p[kt * 256 + nt * 32 + q8r];
                mma_k16(D0, D1, D2, D3,
                        A2[kt][0], A2[kt][1], A2[kt][2], A2[kt][3], bb.x, bb.y);
            }
            const int c0 = nt * 8 + 2 * q;
            uint32_t t01 = h2tanh(h2fma(pack_h2(D0, D1), H05C, hb2h[nt]));
            uint32_t t23 = h2tanh(h2fma(pack_h2(D2, D3), H05C, hb2h[nt]));
            float2 w01 = h22f2(h2fma(t01, H05C, H05C));
            float2 w23 = h22f2(h2fma(t23, H05C, H05C));
            float2 hr0 = *(const float2*)(h0base + c0);
            float2 hr1 = *(const float2*)(h1base + c0);
            acc[nt * 2 + 0] = fmaf(w01.x, hr0.x, acc[nt * 2 + 0]);
            acc[nt * 2 + 0] = fmaf(w23.x, hr1.x, acc[nt * 2 + 0]);
            acc[nt * 2 + 1] = fmaf(w01.y, hr0.y, acc[nt * 2 + 1]);
            acc[nt * 2 + 1] = fmaf(w23.y, hr1.y, acc[nt * 2 + 1]);
            swa[nt * 2 + 0] += w01.x + w23.x;
            swa[nt * 2 + 1] += w01.y + w23.y;
        }
        buf ^= 1;
    }

    // ---- reduce over r-groups (lane bits 2..4), write h_agg to smem ----
    #pragma unroll
    for (int j = 0; j < 16; j++) {
        #pragma unroll
        for (int off = 4; off <= 16; off <<= 1) {
            acc[j] += __shfl_xor_sync(0xffffffffu, acc[j], off);
            swa[j] += __shfl_xor_sync(0xffffffffu, swa[j], off);
        }
    }
    if (lane < 4) {      // r == 0, q = lane
        #pragma unroll
        for (int nt = 0; nt < 8; nt++) {
            int c0 = nt * 8 + 2 * q;
            hagg_s[w][c0]     = acc[nt * 2 + 0] / (swa[nt * 2 + 0] + 1e-6f);
            hagg_s[w][c0 + 1] = acc[nt * 2 + 1] / (swa[nt * 2 + 1] + 1e-6f);
        }
    }
    __syncwarp();

    // =======================================================================
    // Node MLP tail: warp w handles node nrow. Lane owns channels 2*lane, 2*lane+1.
    // =======================================================================
    {
        const int k0 = 2 * lane;
        float2 bn1v = *(const float2*)&bn1[k0];
        float z0 = bn1v.x, z1 = bn1v.y;
        #pragma unroll 8
        for (int i = 0; i < 64; i++) {
            float hv = h_l[nrow * 64 + i];
            float2 wv = *(const float2*)&Wn1[i * 64 + k0];
            z0 = fmaf(hv, wv.x, z0);
            z1 = fmaf(hv, wv.y, z1);
        }
        #pragma unroll 8
        for (int i = 0; i < 64; i++) {
            float hv = hagg_s[w][i];
            float2 wv = *(const float2*)&Wn1[(64 + i) * 64 + k0];
            z0 = fmaf(hv, wv.x, z0);
            z1 = fmaf(hv, wv.y, z1);
        }
        // LayerNorm across the warp (64 channels)
        float s = z0 + z1;
        #pragma unroll
        for (int off = 16; off >= 1; off >>= 1) s += __shfl_xor_sync(0xffffffffu, s, off);
        float mu = s * (1.0f / 64.0f);
        float d0 = z0 - mu, d1 = z1 - mu;
        float v = fmaf(d0, d0, d1 * d1);
        #pragma unroll
        for (int off = 16; off >= 1; off >>= 1) v += __shfl_xor_sync(0xffffffffu, v, off);
        float rstd = rsqrtf(v * (1.0f / 64.0f) + 1e-5f);

        float2 gv = *(const float2*)&ln_g[k0];
        float2 bv = *(const float2*)&ln_b[k0];
        float zn0 = fmaf(d0 * rstd, gv.x, bv.x);
        float zn1 = fmaf(d1 * rstd, gv.y, bv.y);
        float hp0 = 0.5f * zn0, hp1 = 0.5f * zn1;
        ss_s[w][k0]     = fmaf(hp0, tanh_ap(hp0), hp0);
        ss_s[w][k0 + 1] = fmaf(hp1, tanh_ap(hp1), hp1);
        __syncwarp();

        float2 bn2v = *(const float2*)&bn2[k0];
        float o0 = bn2v.x, o1 = bn2v.y;
        #pragma unroll 8
        for (int i = 0; i < 64; i++) {
            float sv = ss_s[w][i];
            float2 wv = *(const float2*)&Wn2[i * 64 + k0];
            o0 = fmaf(sv, wv.x, o0);
            o1 = fmaf(sv, wv.y, o1);
        }
        float2 hlv = *(const float2*)&h_l[nrow * 64 + k0];
        float2 ov;
        ov.x = hlv.x + o0;
        ov.y = hlv.y + o1;
        *(float2*)&out[nrow * 64 + k0] = ov;
    }
}

extern "C" void kernel_launch(void* const* d_in, const int* in_sizes, int n_in,
                              void* d_out, int out_size)
{
    const float* h_l  = (const float*)d_in[0];
    const float* x_l  = (const float*)d_in[1];
    const float* h_r  = (const float*)d_in[2];
    const float* x_r  = (const float*)d_in[3];
    const float* W1   = (const float*)d_in[4];
    const float* b1   = (const float*)d_in[5];
    const float* W2   = (const float*)d_in[6];
    const float* b2   = (const float*)d_in[7];
    const float* Wn1  = (const float*)d_in[8];
    const float* bn1  = (const float*)d_in[9];
    const float* ln_g = (const float*)d_in[10];
    const float* ln_b = (const float*)d_in[11];
    const float* Wn2  = (const float*)d_in[12];
    const float* bn2  = (const float*)d_in[13];
    float* out = (float*)d_out;

    fused_kernel<<<NN / 8, THREADS>>>(h_l, x_l, h_r, x_r, W1, b1, W2, b2,
                                      Wn1, bn1, ln_g, ln_b, Wn2, bn2, out);
}

// round 7
// speedup vs baseline: 6.0129x; 1.1005x over previous
#include <cuda_runtime.h>
#include <cuda_fp16.h>
#include <cstdint>

#define NN 2048
#define MMT 2048
#define WARPS 14
#define THREADS (WARPS * 32)
#define GRID 147
#define TILE_MB 16
#define HRT_MSTR 100     // hr_t m-stride (floats); q-stride 24 (bank-verified)
#define H05C 0x38003800u // half2(0.5, 0.5)

__device__ __forceinline__ float tanh_ap(float x) {
    float y; asm("tanh.approx.f32 %0, %1;" : "=f"(y) : "f"(x)); return y;
}
__device__ __forceinline__ uint32_t pack_h2(float lo, float hi) {
    uint32_t u; asm("cvt.rn.f16x2.f32 %0, %1, %2;" : "=r"(u) : "f"(hi), "f"(lo)); return u;
}
__device__ __forceinline__ uint32_t h2mul(uint32_t a, uint32_t b) {
    uint32_t d; asm("mul.rn.f16x2 %0, %1, %2;" : "=r"(d) : "r"(a), "r"(b)); return d;
}
__device__ __forceinline__ uint32_t h2fma(uint32_t a, uint32_t b, uint32_t c) {
    uint32_t d; asm("fma.rn.f16x2 %0, %1, %2, %3;" : "=r"(d) : "r"(a), "r"(b), "r"(c)); return d;
}
__device__ __forceinline__ uint32_t h2tanh(uint32_t a) {
    uint32_t d; asm("tanh.approx.f16x2 %0, %1;" : "=r"(d) : "r"(a)); return d;
}
__device__ __forceinline__ float2 h22f2(uint32_t u) {
    float2 f;
    asm("{ .reg .b16 lo, hi; mov.b32 {lo, hi}, %2; cvt.f32.f16 %0, lo; cvt.f32.f16 %1, hi; }"
        : "=f"(f.x), "=f"(f.y) : "r"(u));
    return f;
}
__device__ __forceinline__ uint32_t silu_h2(uint32_t p) {
    uint32_t hp = h2mul(p, H05C);
    uint32_t t  = h2tanh(hp);
    return h2fma(hp, t, hp);
}
__device__ __forceinline__ void mma_k8(float* D, uint32_t a0, uint32_t a1, uint32_t b0) {
    asm volatile(
        "mma.sync.aligned.m16n8k8.row.col.f32.f16.f16.f32 "
        "{%0,%1,%2,%3}, {%4,%5}, {%6}, {%0,%1,%2,%3};"
        : "+f"(D[0]), "+f"(D[1]), "+f"(D[2]), "+f"(D[3])
        : "r"(a0), "r"(a1), "r"(b0));
}
__device__ __forceinline__ void mma_k16(float& d0, float& d1, float& d2, float& d3,
                                        uint32_t a0, uint32_t a1, uint32_t a2, uint32_t a3,
                                        uint32_t b0, uint32_t b1) {
    asm volatile(
        "mma.sync.aligned.m16n8k16.row.col.f32.f16.f16.f32 "
        "{%0,%1,%2,%3}, {%4,%5,%6,%7}, {%8,%9}, {%0,%1,%2,%3};"
        : "+f"(d0), "+f"(d1), "+f"(d2), "+f"(d3)
        : "r"(a0), "r"(a1), "r"(a2), "r"(a3), "r"(b0), "r"(b1));
}

// ---------------------------------------------------------------------------
// Fully fused. Grid = 147 CTAs x 448 threads -> exactly 1 CTA/SM, single wave,
// warp w owns node row blockIdx*14 + w (clamped; duplicate rows write identical
// values). Per m-chunk of 16: MMA1 (edge-raw @ W1) -> f16x2 silu -> MMA2
// (hidden @ W2) -> f16x2 sigmoid -> fp32 accumulate. Node MLP fused as tail.
// ---------------------------------------------------------------------------
__global__ void __launch_bounds__(THREADS, 1)
fused_kernel(const float* __restrict__ h_l, const float* __restrict__ x_l,
             const float* __restrict__ h_r, const float* __restrict__ x_r,
             const float* __restrict__ W1, const float* __restrict__ b1,
             const float* __restrict__ W2, const float* __restrict__ b2,
             const float* __restrict__ Wn1, const float* __restrict__ bn1,
             const float* __restrict__ ln_g, const float* __restrict__ ln_b,
             const float* __restrict__ Wn2, const float* __restrict__ bn2,
             float* __restrict__ out)
{
    __shared__ uint4 b4p[2][8][32];            // W2 frags, lane-indexed (conflict-free LDS.128)
    __shared__ float hr_t[2][16 * HRT_MSTR];   // transposed h_r chunk
    __shared__ float xrs[2][48];
    __shared__ float rps[2][48];
    __shared__ float hagg_s[WARPS][64];
    __shared__ float ss_s[WARPS][64];

    const int tid  = threadIdx.x;
    const int w    = tid >> 5;
    const int lane = tid & 31;
    const int r    = lane >> 2;
    const int q    = lane & 3;

    // ---- one-time: W2 fragments, element for consumer lane l = (r=l>>2, q=l&3) ----
    for (int i = tid; i < 512; i += THREADS) {
        int l  = i & 31, nt = (i >> 5) & 7, kp = i >> 8;
        int rr = l >> 2, qq = l & 3;
        int c  = nt * 8 + rr;
        uint4 v;
        {
            int j0 = (2 * kp) * 16 + 2 * qq;
            v.x = pack_h2(W2[j0 * 64 + c],       W2[(j0 + 1) * 64 + c]);
            v.y = pack_h2(W2[(j0 + 8) * 64 + c], W2[(j0 + 9) * 64 + c]);
        }
        {
            int j0 = (2 * kp + 1) * 16 + 2 * qq;
            v.z = pack_h2(W2[j0 * 64 + c],       W2[(j0 + 1) * 64 + c]);
            v.w = pack_h2(W2[(j0 + 8) * 64 + c], W2[(j0 + 9) * 64 + c]);
        }
        b4p[kp][nt][l] = v;
    }
    // ---- one-time: W1 B-fragments (registers) ----
    uint32_t b1f[8];
    #pragma unroll
    for (int nt = 0; nt < 8; nt++) {
        int cc = nt * 8 + r;
        b1f[nt] = (q == 0) ? pack_h2(W1[cc], W1[64 + cc])
                : (q == 1) ? pack_h2(W1[128 + cc], W1[192 + cc] + b1[cc])
                : 0u;
    }
    // ---- one-time: 0.5*b2 as half2 per nt ----
    uint32_t hb2h[8];
    #pragma unroll
    for (int nt = 0; nt < 8; nt++) {
        int c0 = nt * 8 + 2 * q;
        hb2h[nt] = pack_h2(0.5f * b2[c0], 0.5f * b2[c0 + 1]);
    }

    // per-warp n-row invariants (clamped for the ragged last CTA)
    int nrow = blockIdx.x * WARPS + w;
    if (nrow > NN - 1) nrow = NN - 1;
    const float xlx = x_l[nrow * 3 + 0];
    const float xly = x_l[nrow * 3 + 1];
    const float xlz = x_l[nrow * 3 + 2];
    const float l0  = h_l[nrow * 64 + 61];
    const float l1  = h_l[nrow * 64 + 62];
    const float l2  = h_l[nrow * 64 + 63];

    const int mi0 = r, mi1 = r + 8;

    float acc[16], swa[16];
    #pragma unroll
    for (int i = 0; i < 16; i++) { acc[i] = 0.f; swa[i] = 0.f; }

    // ---- chunk loader: h_r transposed to [m][q*24 + nt*2 + u] ----
    #define LOAD_CHUNK(m0_, buf_) do {                                          \
        if (tid < 48) xrs[buf_][tid] = x_r[(m0_) * 3 + tid];                    \
        else if (tid < 96) {                                                    \
            int t = tid - 48;                                                   \
            rps[buf_][t] = h_r[((m0_) + t / 3) * 64 + 61 + t % 3];              \
        }                                                                       \
        if (tid < 256) {                                                        \
            int mm = tid >> 4, k = tid & 15;                                    \
            float4 v = ((const float4*)(h_r + (m0_) * 64))[tid];                \
            float* dst = &hr_t[buf_][mm * HRT_MSTR];                            \
            int c0 = k * 4;                                                     \
            int q0 = (c0 & 7) >> 1, j0 = (c0 >> 3) * 2;                         \
            *(float2*)&dst[q0 * 24 + j0] = make_float2(v.x, v.y);               \
            int c2 = c0 + 2;                                                    \
            int q2 = (c2 & 7) >> 1, j2 = (c2 >> 3) * 2;                         \
            *(float2*)&dst[q2 * 24 + j2] = make_float2(v.z, v.w);               \
        }                                                                       \
    } while (0)

    LOAD_CHUNK(0, 0);
    int buf = 0;

    for (int chunk = 0; chunk < MMT / TILE_MB; chunk++) {
        __syncthreads();
        if (chunk + 1 < MMT / TILE_MB) LOAD_CHUNK((chunk + 1) * TILE_MB, buf ^ 1);

        const float* xr = xrs[buf];
        const float* rp = rps[buf];
        const float* p0 = &hr_t[buf][mi0 * HRT_MSTR + q * 24];
        const float* p1 = &hr_t[buf][mi1 * HRT_MSTR + q * 24];

        // ---- edge scalars for this lane's two m-rows ----
        float a0v, bh0, ch0, a1v, bh1, ch1;
        {
            float dx = xlx - xr[mi0 * 3 + 0];
            float dy = xly - xr[mi0 * 3 + 1];
            float dz = xlz - xr[mi0 * 3 + 2];
            float d2 = fmaf(dx, dx, fmaf(dy, dy, dz * dz));
            a0v = __expf(-0.2f * d2);
            bh0 = fmaf(l0, rp[mi0 * 3 + 1], l1 * rp[mi0 * 3 + 0]);
            ch0 = l2 * rp[mi0 * 3 + 2];
        }
        {
            float dx = xlx - xr[mi1 * 3 + 0];
            float dy = xly - xr[mi1 * 3 + 1];
            float dz = xlz - xr[mi1 * 3 + 2];
            float d2 = fmaf(dx, dx, fmaf(dy, dy, dz * dz));
            a1v = __expf(-0.2f * d2);
            bh1 = fmaf(l0, rp[mi1 * 3 + 1], l1 * rp[mi1 * 3 + 0]);
            ch1 = l2 * rp[mi1 * 3 + 2];
        }

        // ---- ER A-fragments for MMA1 ----
        float e00 = (q == 0) ? a0v : (q == 1) ? ch0 : 0.f;
        float e01 = (q == 0) ? bh0 : (q == 1) ? 1.f : 0.f;
        float e10 = (q == 0) ? a1v : (q == 1) ? ch1 : 0.f;
        float e11 = (q == 0) ? bh1 : (q == 1) ? 1.f : 0.f;
        uint32_t A10 = pack_h2(e00, e01);
        uint32_t A11 = pack_h2(e10, e11);

        // ---- MMA1 + f16x2 silu -> MMA2 A-fragments ----
        uint32_t A2[4][4];
        #pragma unroll
        for (int kt = 0; kt < 4; kt++) {
            float P0[4] = {0.f, 0.f, 0.f, 0.f};
            float P1[4] = {0.f, 0.f, 0.f, 0.f};
            mma_k8(P0, A10, A11, b1f[2 * kt]);
            mma_k8(P1, A10, A11, b1f[2 * kt + 1]);
            A2[kt][0] = silu_h2(pack_h2(P0[0], P0[1]));
            A2[kt][1] = silu_h2(pack_h2(P0[2], P0[3]));
            A2[kt][2] = silu_h2(pack_h2(P1[0], P1[1]));
            A2[kt][3] = silu_h2(pack_h2(P1[2], P1[3]));
        }

        // ---- MMA2 + f16x2 sigmoid + fp32 accumulate, per nt-pair ----
        #pragma unroll
        for (int np = 0; np < 4; np++) {
            float4 h0p = *(const float4*)(p0 + np * 4);   // {nt=2np:(c0,c0+1), nt=2np+1:(c0,c0+1)} row mi0
            float4 h1p = *(const float4*)(p1 + np * 4);   // same, row mi1
            #pragma unroll
            for (int s = 0; s < 2; s++) {
                const int nt = np * 2 + s;
                float D0 = 0.f, D1 = 0.f, D2 = 0.f, D3 = 0.f;
                uint4 B0 = b4p[0][nt][lane];
                uint4 B1 = b4p[1][nt][lane];
                mma_k16(D0, D1, D2, D3, A2[0][0], A2[0][1], A2[0][2], A2[0][3], B0.x, B0.y);
                mma_k16(D0, D1, D2, D3, A2[1][0], A2[1][1], A2[1][2], A2[1][3], B0.z, B0.w);
                mma_k16(D0, D1, D2, D3, A2[2][0], A2[2][1], A2[2][2], A2[2][3], B1.x, B1.y);
                mma_k16(D0, D1, D2, D3, A2[3][0], A2[3][1], A2[3][2], A2[3][3], B1.z, B1.w);

                uint32_t t01 = h2tanh(h2fma(pack_h2(D0, D1), H05C, hb2h[nt]));
                uint32_t t23 = h2tanh(h2fma(pack_h2(D2, D3), H05C, hb2h[nt]));
                float2 w01 = h22f2(h2fma(t01, H05C, H05C));
                float2 w23 = h22f2(h2fma(t23, H05C, H05C));
                float hx0 = s ? h0p.z : h0p.x, hy0 = s ? h0p.w : h0p.y;
                float hx1 = s ? h1p.z : h1p.x, hy1 = s ? h1p.w : h1p.y;
                acc[nt * 2 + 0] = fmaf(w01.x, hx0, acc[nt * 2 + 0]);
                acc[nt * 2 + 0] = fmaf(w23.x, hx1, acc[nt * 2 + 0]);
                acc[nt * 2 + 1] = fmaf(w01.y, hy0, acc[nt * 2 + 1]);
                acc[nt * 2 + 1] = fmaf(w23.y, hy1, acc[nt * 2 + 1]);
                swa[nt * 2 + 0] += w01.x + w23.x;
                swa[nt * 2 + 1] += w01.y + w23.y;
            }
        }
        buf ^= 1;
    }

    // ---- reduce over r-groups, write h_agg to smem ----
    #pragma unroll
    for (int j = 0; j < 16; j++) {
        #pragma unroll
        for (int off = 4; off <= 16; off <<= 1) {
            acc[j] += __shfl_xor_sync(0xffffffffu, acc[j], off);
            swa[j] += __shfl_xor_sync(0xffffffffu, swa[j], off);
        }
    }
    if (lane < 4) {      // r == 0, q = lane
        #pragma unroll
        for (int nt = 0; nt < 8; nt++) {
            int c0 = nt * 8 + 2 * q;
            hagg_s[w][c0]     = acc[nt * 2 + 0] / (swa[nt * 2 + 0] + 1e-6f);
            hagg_s[w][c0 + 1] = acc[nt * 2 + 1] / (swa[nt * 2 + 1] + 1e-6f);
        }
    }
    __syncwarp();

    // ==== node MLP tail: warp w = node nrow; lane owns channels 2*lane, 2*lane+1 ====
    {
        const int k0 = 2 * lane;
        float2 bn1v = *(const float2*)&bn1[k0];
        float z0 = bn1v.x, z1 = bn1v.y;
        #pragma unroll 8
        for (int i = 0; i < 64; i++) {
            float hv = h_l[nrow * 64 + i];
            float2 wv = *(const float2*)&Wn1[i * 64 + k0];
            z0 = fmaf(hv, wv.x, z0);
            z1 = fmaf(hv, wv.y, z1);
        }
        #pragma unroll 8
        for (int i = 0; i < 64; i++) {
            float hv = hagg_s[w][i];
            float2 wv = *(const float2*)&Wn1[(64 + i) * 64 + k0];
            z0 = fmaf(hv, wv.x, z0);
            z1 = fmaf(hv, wv.y, z1);
        }
        float s = z0 + z1;
        #pragma unroll
        for (int off = 16; off >= 1; off >>= 1) s += __shfl_xor_sync(0xffffffffu, s, off);
        float mu = s * (1.0f / 64.0f);
        float d0 = z0 - mu, d1 = z1 - mu;
        float v = fmaf(d0, d0, d1 * d1);
        #pragma unroll
        for (int off = 16; off >= 1; off >>= 1) v += __shfl_xor_sync(0xffffffffu, v, off);
        float rstd = rsqrtf(v * (1.0f / 64.0f) + 1e-5f);

        float2 gv = *(const float2*)&ln_g[k0];
        float2 bv = *(const float2*)&ln_b[k0];
        float zn0 = fmaf(d0 * rstd, gv.x, bv.x);
        float zn1 = fmaf(d1 * rstd, gv.y, bv.y);
        float hp0 = 0.5f * zn0, hp1 = 0.5f * zn1;
        ss_s[w][k0]     = fmaf(hp0, tanh_ap(hp0), hp0);
        ss_s[w][k0 + 1] = fmaf(hp1, tanh_ap(hp1), hp1);
        __syncwarp();

        float2 bn2v = *(const float2*)&bn2[k0];
        float o0 = bn2v.x, o1 = bn2v.y;
        #pragma unroll 8
        for (int i = 0; i < 64; i++) {
            float sv = ss_s[w][i];
            float2 wv = *(const float2*)&Wn2[i * 64 + k0];
            o0 = fmaf(sv, wv.x, o0);
            o1 = fmaf(sv, wv.y, o1);
        }
        float2 hlv = *(const float2*)&h_l[nrow * 64 + k0];
        float2 ov;
        ov.x = hlv.x + o0;
        ov.y = hlv.y + o1;
        *(float2*)&out[nrow * 64 + k0] = ov;
    }
}

extern "C" void kernel_launch(void* const* d_in, const int* in_sizes, int n_in,
                              void* d_out, int out_size)
{
    const float* h_l  = (const float*)d_in[0];
    const float* x_l  = (const float*)d_in[1];
    const float* h_r  = (const float*)d_in[2];
    const float* x_r  = (const float*)d_in[3];
    const float* W1   = (const float*)d_in[4];
    const float* b1   = (const float*)d_in[5];
    const float* W2   = (const float*)d_in[6];
    const float* b2   = (const float*)d_in[7];
    const float* Wn1  = (const float*)d_in[8];
    const float* bn1  = (const float*)d_in[9];
    const float* ln_g = (const float*)d_in[10];
    const float* ln_b = (const float*)d_in[11];
    const float* Wn2  = (const float*)d_in[12];
    const float* bn2  = (const float*)d_in[13];
    float* out = (float*)d_out;

    fused_kernel<<<GRID, THREADS>>>(h_l, x_l, h_r, x_r, W1, b1, W2, b2,
                                    Wn1, bn1, ln_g, ln_b, Wn2, bn2, out);
}

// round 8
// speedup vs baseline: 6.4457x; 1.0720x over previous
#include <cuda_runtime.h>
#include <cuda_fp16.h>
#include <cstdint>

#define NN 2048
#define MMT 2048
#define WARPS 14
#define THREADS (WARPS * 32)
#define GRID 147
#define TILE_MB 16
#define HRT_MSTR 100     // hr_t m-stride (floats); q-stride 24 (bank-verified)
#define H05C 0x38003800u // half2(0.5, 0.5)

__device__ float g_part[16 * 64];
__device__ float g_sumH[64];

__device__ __forceinline__ float tanh_ap(float x) {
    float y; asm("tanh.approx.f32 %0, %1;" : "=f"(y) : "f"(x)); return y;
}
__device__ __forceinline__ uint32_t pack_h2(float lo, float hi) {
    uint32_t u; asm("cvt.rn.f16x2.f32 %0, %1, %2;" : "=r"(u) : "f"(hi), "f"(lo)); return u;
}
__device__ __forceinline__ uint32_t h2mul(uint32_t a, uint32_t b) {
    uint32_t d; asm("mul.rn.f16x2 %0, %1, %2;" : "=r"(d) : "r"(a), "r"(b)); return d;
}
__device__ __forceinline__ uint32_t h2add(uint32_t a, uint32_t b) {
    uint32_t d; asm("add.rn.f16x2 %0, %1, %2;" : "=r"(d) : "r"(a), "r"(b)); return d;
}
__device__ __forceinline__ uint32_t h2fma(uint32_t a, uint32_t b, uint32_t c) {
    uint32_t d; asm("fma.rn.f16x2 %0, %1, %2, %3;" : "=r"(d) : "r"(a), "r"(b), "r"(c)); return d;
}
__device__ __forceinline__ uint32_t h2tanh(uint32_t a) {
    uint32_t d; asm("tanh.approx.f16x2 %0, %1;" : "=r"(d) : "r"(a)); return d;
}
__device__ __forceinline__ float2 h22f2(uint32_t u) {
    float2 f;
    asm("{ .reg .b16 lo, hi; mov.b32 {lo, hi}, %2; cvt.f32.f16 %0, lo; cvt.f32.f16 %1, hi; }"
        : "=f"(f.x), "=f"(f.y) : "r"(u));
    return f;
}
__device__ __forceinline__ uint32_t silu_h2(uint32_t p) {
    uint32_t hp = h2mul(p, H05C);
    uint32_t t  = h2tanh(hp);
    return h2fma(hp, t, hp);
}
// f16-accumulator MMAs: D/C are f16x2 pairs (exactly the packed layout we consume)
__device__ __forceinline__ void mma_k8h(uint32_t& d0, uint32_t& d1,
                                        uint32_t a0, uint32_t a1, uint32_t b0) {
    asm volatile(
        "mma.sync.aligned.m16n8k8.row.col.f16.f16.f16.f16 "
        "{%0,%1}, {%2,%3}, {%4}, {%0,%1};"
        : "+r"(d0), "+r"(d1) : "r"(a0), "r"(a1), "r"(b0));
}
__device__ __forceinline__ void mma_k16h(uint32_t& d0, uint32_t& d1,
                                         uint32_t a0, uint32_t a1, uint32_t a2, uint32_t a3,
                                         uint32_t b0, uint32_t b1) {
    asm volatile(
        "mma.sync.aligned.m16n8k16.row.col.f16.f16.f16.f16 "
        "{%0,%1}, {%2,%3,%4,%5}, {%6,%7}, {%0,%1};"
        : "+r"(d0), "+r"(d1)
        : "r"(a0), "r"(a1), "r"(a2), "r"(a3), "r"(b0), "r"(b1));
}

// ---------------------------------------------------------------------------
// sumH pre-kernels: g_sumH[c] = sum_m h_r[m][c]  (deterministic fixed-order tree)
// ---------------------------------------------------------------------------
__global__ void sumh_k1(const float* __restrict__ h_r) {
    __shared__ float p[256];
    const int tid = threadIdx.x;
    const int c = tid & 63, rq = tid >> 6;
    float s = 0.f;
    const int mbase = blockIdx.x * 128 + rq * 32;
    #pragma unroll 8
    for (int i = 0; i < 32; i++) s += h_r[(mbase + i) * 64 + c];
    p[tid] = s;
    __syncthreads();
    if (tid < 64)
        g_part[blockIdx.x * 64 + tid] = (p[tid] + p[tid + 64]) + (p[tid + 128] + p[tid + 192]);
}
__global__ void sumh_k2() {
    const int c = threadIdx.x;
    float s = 0.f;
    #pragma unroll
    for (int k = 0; k < 16; k++) s += g_part[k * 64 + c];
    g_sumH[c] = s;
}

// ---------------------------------------------------------------------------
// Fused kernel: grid 147 x 448, warp w owns node row blockIdx*14+w (clamped).
// Per 16-m chunk: MMA1(f16 acc) -> silu(f16x2) -> MMA2(f16 acc) ->
// t = tanh(0.5E+0.5b2); accumulate t*h_r (f32) and t (f16x2, 8-chunk flush).
// h_agg = (0.5*acc + 0.5*sumH) / (0.5*swa + 1024 + 1e-6). Node MLP fused tail.
// ---------------------------------------------------------------------------
__global__ void __launch_bounds__(THREADS, 1)
fused_kernel(const float* __restrict__ h_l, const float* __restrict__ x_l,
             const float* __restrict__ h_r, const float* __restrict__ x_r,
             const float* __restrict__ W1, const float* __restrict__ b1,
             const float* __restrict__ W2, const float* __restrict__ b2,
             const float* __restrict__ Wn1, const float* __restrict__ bn1,
             const float* __restrict__ ln_g, const float* __restrict__ ln_b,
             const float* __restrict__ Wn2, const float* __restrict__ bn2,
             float* __restrict__ out)
{
    __shared__ uint4 b4p[2][8][32];            // W2 frags, lane-indexed (conflict-free LDS.128)
    __shared__ float hr_t[2][16 * HRT_MSTR];   // transposed h_r chunk
    __shared__ float xrs[2][48];
    __shared__ float rps[2][48];
    __shared__ float hagg_s[WARPS][64];
    __shared__ float ss_s[WARPS][64];

    const int tid  = threadIdx.x;
    const int w    = tid >> 5;
    const int lane = tid & 31;
    const int r    = lane >> 2;
    const int q    = lane & 3;

    // ---- one-time: W2 fragments, element for consumer lane l = (r=l>>2, q=l&3) ----
    for (int i = tid; i < 512; i += THREADS) {
        int l  = i & 31, nt = (i >> 5) & 7, kp = i >> 8;
        int rr = l >> 2, qq = l & 3;
        int c  = nt * 8 + rr;
        uint4 v;
        {
            int j0 = (2 * kp) * 16 + 2 * qq;
            v.x = pack_h2(W2[j0 * 64 + c],       W2[(j0 + 1) * 64 + c]);
            v.y = pack_h2(W2[(j0 + 8) * 64 + c], W2[(j0 + 9) * 64 + c]);
        }
        {
            int j0 = (2 * kp + 1) * 16 + 2 * qq;
            v.z = pack_h2(W2[j0 * 64 + c],       W2[(j0 + 1) * 64 + c]);
            v.w = pack_h2(W2[(j0 + 8) * 64 + c], W2[(j0 + 9) * 64 + c]);
        }
        b4p[kp][nt][l] = v;
    }
    // ---- one-time: W1 B-fragments (registers) ----
    uint32_t b1f[8];
    #pragma unroll
    for (int nt = 0; nt < 8; nt++) {
        int cc = nt * 8 + r;
        b1f[nt] = (q == 0) ? pack_h2(W1[cc], W1[64 + cc])
                : (q == 1) ? pack_h2(W1[128 + cc], W1[192 + cc] + b1[cc])
                : 0u;
    }
    // ---- one-time: 0.5*b2 as half2 per nt ----
    uint32_t hb2h[8];
    #pragma unroll
    for (int nt = 0; nt < 8; nt++) {
        int c0 = nt * 8 + 2 * q;
        hb2h[nt] = pack_h2(0.5f * b2[c0], 0.5f * b2[c0 + 1]);
    }

    // per-warp n-row invariants (clamped for the ragged last CTA)
    int nrow = blockIdx.x * WARPS + w;
    if (nrow > NN - 1) nrow = NN - 1;
    const float xlx = x_l[nrow * 3 + 0];
    const float xly = x_l[nrow * 3 + 1];
    const float xlz = x_l[nrow * 3 + 2];
    const float l0  = h_l[nrow * 64 + 61];
    const float l1  = h_l[nrow * 64 + 62];
    const float l2  = h_l[nrow * 64 + 63];

    const int mi0 = r, mi1 = r + 8;

    float acc[16], swaf[16];
    uint32_t sswa[8];
    #pragma unroll
    for (int i = 0; i < 16; i++) { acc[i] = 0.f; swaf[i] = 0.f; }
    #pragma unroll
    for (int i = 0; i < 8; i++) sswa[i] = 0u;

    #define LOAD_CHUNK(m0_, buf_) do {                                          \
        if (tid < 48) xrs[buf_][tid] = x_r[(m0_) * 3 + tid];                    \
        else if (tid < 96) {                                                    \
            int t = tid - 48;                                                   \
            rps[buf_][t] = h_r[((m0_) + t / 3) * 64 + 61 + t % 3];              \
        }                                                                       \
        if (tid < 256) {                                                        \
            int mm = tid >> 4, k = tid & 15;                                    \
            float4 v = ((const float4*)(h_r + (m0_) * 64))[tid];                \
            float* dst = &hr_t[buf_][mm * HRT_MSTR];                            \
            int c0 = k * 4;                                                     \
            int q0 = (c0 & 7) >> 1, j0 = (c0 >> 3) * 2;                         \
            *(float2*)&dst[q0 * 24 + j0] = make_float2(v.x, v.y);               \
            int c2 = c0 + 2;                                                    \
            int q2 = (c2 & 7) >> 1, j2 = (c2 >> 3) * 2;                         \
            *(float2*)&dst[q2 * 24 + j2] = make_float2(v.z, v.w);               \
        }                                                                       \
    } while (0)

    LOAD_CHUNK(0, 0);
    int buf = 0;

    for (int chunk = 0; chunk < MMT / TILE_MB; chunk++) {
        __syncthreads();
        if (chunk + 1 < MMT / TILE_MB) LOAD_CHUNK((chunk + 1) * TILE_MB, buf ^ 1);

        const float* xr = xrs[buf];
        const float* rp = rps[buf];
        const float* p0 = &hr_t[buf][mi0 * HRT_MSTR + q * 24];
        const float* p1 = &hr_t[buf][mi1 * HRT_MSTR + q * 24];

        // ---- edge scalars for this lane's two m-rows ----
        float a0v, bh0, ch0, a1v, bh1, ch1;
        {
            float dx = xlx - xr[mi0 * 3 + 0];
            float dy = xly - xr[mi0 * 3 + 1];
            float dz = xlz - xr[mi0 * 3 + 2];
            float d2 = fmaf(dx, dx, fmaf(dy, dy, dz * dz));
            a0v = __expf(-0.2f * d2);
            bh0 = fmaf(l0, rp[mi0 * 3 + 1], l1 * rp[mi0 * 3 + 0]);
            ch0 = l2 * rp[mi0 * 3 + 2];
        }
        {
            float dx = xlx - xr[mi1 * 3 + 0];
            float dy = xly - xr[mi1 * 3 + 1];
            float dz = xlz - xr[mi1 * 3 + 2];
            float d2 = fmaf(dx, dx, fmaf(dy, dy, dz * dz));
            a1v = __expf(-0.2f * d2);
            bh1 = fmaf(l0, rp[mi1 * 3 + 1], l1 * rp[mi1 * 3 + 0]);
            ch1 = l2 * rp[mi1 * 3 + 2];
        }

        // ---- ER A-fragments for MMA1 ----
        float e00 = (q == 0) ? a0v : (q == 1) ? ch0 : 0.f;
        float e01 = (q == 0) ? bh0 : (q == 1) ? 1.f : 0.f;
        float e10 = (q == 0) ? a1v : (q == 1) ? ch1 : 0.f;
        float e11 = (q == 0) ? bh1 : (q == 1) ? 1.f : 0.f;
        uint32_t A10 = pack_h2(e00, e01);
        uint32_t A11 = pack_h2(e10, e11);

        // ---- MMA1 (f16 acc) + silu -> MMA2 A-fragments directly ----
        uint32_t A2[4][4];
        #pragma unroll
        for (int kt = 0; kt < 4; kt++) {
            uint32_t p00 = 0u, p01 = 0u, p10 = 0u, p11 = 0u;
            mma_k8h(p00, p01, A10, A11, b1f[2 * kt]);
            mma_k8h(p10, p11, A10, A11, b1f[2 * kt + 1]);
            A2[kt][0] = silu_h2(p00);   // row r,   k = 16kt+2q..
            A2[kt][1] = silu_h2(p01);   // row r+8
            A2[kt][2] = silu_h2(p10);   // row r,   k = 16kt+8+2q..
            A2[kt][3] = silu_h2(p11);   // row r+8
        }

        // ---- MMA2 (f16 acc) + tanh + accumulate t*h (f32) and t (f16x2) ----
        #pragma unroll
        for (int np = 0; np < 4; np++) {
            float4 h0p = *(const float4*)(p0 + np * 4);
            float4 h1p = *(const float4*)(p1 + np * 4);
            #pragma unroll
            for (int s = 0; s < 2; s++) {
                const int nt = np * 2 + s;
                uint32_t D01 = 0u, D23 = 0u;
                uint4 B0 = b4p[0][nt][lane];
                uint4 B1 = b4p[1][nt][lane];
                mma_k16h(D01, D23, A2[0][0], A2[0][1], A2[0][2], A2[0][3], B0.x, B0.y);
                mma_k16h(D01, D23, A2[1][0], A2[1][1], A2[1][2], A2[1][3], B0.z, B0.w);
                mma_k16h(D01, D23, A2[2][0], A2[2][1], A2[2][2], A2[2][3], B1.x, B1.y);
                mma_k16h(D01, D23, A2[3][0], A2[3][1], A2[3][2], A2[3][3], B1.z, B1.w);

                uint32_t t01 = h2tanh(h2fma(D01, H05C, hb2h[nt]));   // rows mi0 (c0,c1)
                uint32_t t23 = h2tanh(h2fma(D23, H05C, hb2h[nt]));   // rows mi1
                float2 tf0 = h22f2(t01);
                float2 tf1 = h22f2(t23);
                float hx0 = s ? h0p.z : h0p.x, hy0 = s ? h0p.w : h0p.y;
                float hx1 = s ? h1p.z : h1p.x, hy1 = s ? h1p.w : h1p.y;
                acc[nt * 2 + 0] = fmaf(tf0.x, hx0, acc[nt * 2 + 0]);
                acc[nt * 2 + 0] = fmaf(tf1.x, hx1, acc[nt * 2 + 0]);
                acc[nt * 2 + 1] = fmaf(tf0.y, hy0, acc[nt * 2 + 1]);
                acc[nt * 2 + 1] = fmaf(tf1.y, hy1, acc[nt * 2 + 1]);
                sswa[nt] = h2add(sswa[nt], h2add(t01, t23));
            }
        }
        // ---- flush f16 t-sums every 8 chunks (|partial| <= 32, exact enough) ----
        if ((chunk & 7) == 7) {
            #pragma unroll
            for (int nt = 0; nt < 8; nt++) {
                float2 s = h22f2(sswa[nt]);
                swaf[nt * 2 + 0] += s.x;
                swaf[nt * 2 + 1] += s.y;
                sswa[nt] = 0u;
            }
        }
        buf ^= 1;
    }

    // ---- reduce over r-groups, form h_agg ----
    #pragma unroll
    for (int j = 0; j < 16; j++) {
        #pragma unroll
        for (int off = 4; off <= 16; off <<= 1) {
            acc[j]  += __shfl_xor_sync(0xffffffffu, acc[j], off);
            swaf[j] += __shfl_xor_sync(0xffffffffu, swaf[j], off);
        }
    }
    if (lane < 4) {      // r == 0, q = lane
        #pragma unroll
        for (int nt = 0; nt < 8; nt++) {
            int c0 = nt * 8 + 2 * q;
            float num0 = fmaf(0.5f, acc[nt * 2 + 0], 0.5f * g_sumH[c0]);
            float num1 = fmaf(0.5f, acc[nt * 2 + 1], 0.5f * g_sumH[c0 + 1]);
            float den0 = fmaf(0.5f, swaf[nt * 2 + 0], 1024.0f + 1e-6f);
            float den1 = fmaf(0.5f, swaf[nt * 2 + 1], 1024.0f + 1e-6f);
            hagg_s[w][c0]     = num0 / den0;
            hagg_s[w][c0 + 1] = num1 / den1;
        }
    }
    __syncwarp();

    // ==== node MLP tail: warp w = node nrow; lane owns channels 2*lane, 2*lane+1 ====
    {
        const int k0 = 2 * lane;
        float2 bn1v = *(const float2*)&bn1[k0];
        float z0 = bn1v.x, z1 = bn1v.y;
        #pragma unroll 8
        for (int i = 0; i < 64; i++) {
            float hv = h_l[nrow * 64 + i];
            float2 wv = *(const float2*)&Wn1[i * 64 + k0];
            z0 = fmaf(hv, wv.x, z0);
            z1 = fmaf(hv, wv.y, z1);
        }
        #pragma unroll 8
        for (int i = 0; i < 64; i++) {
            float hv = hagg_s[w][i];
            float2 wv = *(const float2*)&Wn1[(64 + i) * 64 + k0];
            z0 = fmaf(hv, wv.x, z0);
            z1 = fmaf(hv, wv.y, z1);
        }
        float s = z0 + z1;
        #pragma unroll
        for (int off = 16; off >= 1; off >>= 1) s += __shfl_xor_sync(0xffffffffu, s, off);
        float mu = s * (1.0f / 64.0f);
        float d0 = z0 - mu, d1 = z1 - mu;
        float v = fmaf(d0, d0, d1 * d1);
        #pragma unroll
        for (int off = 16; off >= 1; off >>= 1) v += __shfl_xor_sync(0xffffffffu, v, off);
        float rstd = rsqrtf(v * (1.0f / 64.0f) + 1e-5f);

        float2 gv = *(const float2*)&ln_g[k0];
        float2 bv = *(const float2*)&ln_b[k0];
        float zn0 = fmaf(d0 * rstd, gv.x, bv.x);
        float zn1 = fmaf(d1 * rstd, gv.y, bv.y);
        float hp0 = 0.5f * zn0, hp1 = 0.5f * zn1;
        ss_s[w][k0]     = fmaf(hp0, tanh_ap(hp0), hp0);
        ss_s[w][k0 + 1] = fmaf(hp1, tanh_ap(hp1), hp1);
        __syncwarp();

        float2 bn2v = *(const float2*)&bn2[k0];
        float o0 = bn2v.x, o1 = bn2v.y;
        #pragma unroll 8
        for (int i = 0; i < 64; i++) {
            float sv = ss_s[w][i];
            float2 wv = *(const float2*)&Wn2[i * 64 + k0];
            o0 = fmaf(sv, wv.x, o0);
            o1 = fmaf(sv, wv.y, o1);
        }
        float2 hlv = *(const float2*)&h_l[nrow * 64 + k0];
        float2 ov;
        ov.x = hlv.x + o0;
        ov.y = hlv.y + o1;
        *(float2*)&out[nrow * 64 + k0] = ov;
    }
}

extern "C" void kernel_launch(void* const* d_in, const int* in_sizes, int n_in,
                              void* d_out, int out_size)
{
    const float* h_l  = (const float*)d_in[0];
    const float* x_l  = (const float*)d_in[1];
    const float* h_r  = (const float*)d_in[2];
    const float* x_r  = (const float*)d_in[3];
    const float* W1   = (const float*)d_in[4];
    const float* b1   = (const float*)d_in[5];
    const float* W2   = (const float*)d_in[6];
    const float* b2   = (const float*)d_in[7];
    const float* Wn1  = (const float*)d_in[8];
    const float* bn1  = (const float*)d_in[9];
    const float* ln_g = (const float*)d_in[10];
    const float* ln_b = (const float*)d_in[11];
    const float* Wn2  = (const float*)d_in[12];
    const float* bn2  = (const float*)d_in[13];
    float* out = (float*)d_out;

    sumh_k1<<<16, 256>>>(h_r);
    sumh_k2<<<1, 64>>>();
    fused_kernel<<<GRID, THREADS>>>(h_l, x_l, h_r, x_r, W1, b1, W2, b2,
                                    Wn1, bn1, ln_g, ln_b, Wn2, bn2, out);
}